// round 16
// baseline (speedup 1.0000x reference)
#include <cuda_runtime.h>
#include <cstdint>

#define NPTS   16384
#define NPOINT 1024
#define NBATCH 4
#define NTHR   512
#define NWARP  16
#define CHUNKS 8                 // float4 chunks per thread (4 pts each)
#define PPT    32                // points per thread
#define CELLS  64                // 4x4x4 spatial cells

// ---- packed f32x2 helpers (per-lane bit-identical to scalar rn ops) ----
#define PACK2(out, lo, hi) \
    asm("mov.b64 %0, {%1, %2};" : "=l"(out) : "f"(lo), "f"(hi))
#define UNPACK2(lo, hi, in) \
    asm("mov.b64 {%0, %1}, %2;" : "=f"(lo), "=f"(hi) : "l"(in))
#define ADD2(out, a, b) \
    asm("add.rn.f32x2 %0, %1, %2;" : "=l"(out) : "l"(a), "l"(b))
#define MUL2(out, a, b) \
    asm("mul.rn.f32x2 %0, %1, %2;" : "=l"(out) : "l"(a), "l"(b))
#define FMA2(out, a, b, c) \
    asm("fma.rn.f32x2 %0, %1, %2, %3;" : "=l"(out) : "l"(a), "l"(b), "l"(c))

// sorted scratch (written fully every launch before use; output is
// invariant to the nondeterministic within-cell placement, because
// distances are per-point pure functions and the argmax tie-break uses
// ORIGINAL indices via g_pm)
__device__ float    g_xs[NBATCH][NPTS];
__device__ float    g_ys[NBATCH][NPTS];
__device__ float    g_zs[NBATCH][NPTS];
__device__ unsigned g_pm[NBATCH][NPTS];

__device__ __forceinline__ int cell_of(float x, float y, float z) {
    int ix = (int)(x * 4.0f); ix = ix > 3 ? 3 : ix;
    int iy = (int)(y * 4.0f); iy = iy > 3 ? 3 : iy;
    int iz = (int)(z * 4.0f); iz = iz > 3 ? 3 : iz;
    return ix * 16 + iy * 4 + iz;
}

// ---------------------------------------------------------------------------
__global__ void __launch_bounds__(NTHR, 1)
fps_kernel(const float* __restrict__ xyz, float* __restrict__ out) {
    __shared__ unsigned s_v[2][NWARP];
    __shared__ unsigned s_i[2][NWARP];
    __shared__ float    s_cx[2][NWARP], s_cy[2][NWARP], s_cz[2][NWARP];
    __shared__ int      s_cent[NPOINT];
    __shared__ unsigned s_hist[CELLS];

    const int tid  = threadIdx.x;
    const int warp = tid >> 5;
    const int lane = tid & 31;
    const int b    = blockIdx.x;

    const float* __restrict__ base = xyz + (size_t)b * 3 * NPTS;
    const float4* __restrict__ X4o = (const float4*)base;
    const float4* __restrict__ Y4o = X4o + NPTS / 4;
    const float4* __restrict__ Z4o = Y4o + NPTS / 4;

    // ---------------- phase 1: histogram + initial x-argmax ----------------
    if (tid < CELLS) s_hist[tid] = 0;
    __syncthreads();
    float mv0 = -1.0f; int mi0 = 0;
    #pragma unroll
    for (int c = 0; c < CHUNKS; c++) {
        const float4 X = __ldg(&X4o[c * NTHR + tid]);
        const float4 Y = __ldg(&Y4o[c * NTHR + tid]);
        const float4 Z = __ldg(&Z4o[c * NTHR + tid]);
        const float xs[4] = {X.x, X.y, X.z, X.w};
        const float ys[4] = {Y.x, Y.y, Y.z, Y.w};
        const float zs[4] = {Z.x, Z.y, Z.z, Z.w};
        const int p = (c * NTHR + tid) * 4;
        #pragma unroll
        for (int e = 0; e < 4; e++) {
            atomicAdd(&s_hist[cell_of(xs[e], ys[e], zs[e])], 1u);
            if (xs[e] > mv0) { mv0 = xs[e]; mi0 = p + e; }
        }
    }
    __syncthreads();
    if (tid == 0) {                      // exclusive prefix -> cursors
        unsigned run = 0;
        #pragma unroll
        for (int c = 0; c < CELLS; c++) {
            const unsigned t = s_hist[c]; s_hist[c] = run; run += t;
        }
    }
    __syncthreads();

    // ---------------- phase 2: scatter into sorted scratch -----------------
    #pragma unroll
    for (int c = 0; c < CHUNKS; c++) {
        const float4 X = __ldg(&X4o[c * NTHR + tid]);
        const float4 Y = __ldg(&Y4o[c * NTHR + tid]);
        const float4 Z = __ldg(&Z4o[c * NTHR + tid]);
        const float xs[4] = {X.x, X.y, X.z, X.w};
        const float ys[4] = {Y.x, Y.y, Y.z, Y.w};
        const float zs[4] = {Z.x, Z.y, Z.z, Z.w};
        const int p = (c * NTHR + tid) * 4;
        #pragma unroll
        for (int e = 0; e < 4; e++) {
            const unsigned slot =
                atomicAdd(&s_hist[cell_of(xs[e], ys[e], zs[e])], 1u);
            g_xs[b][slot] = xs[e];
            g_ys[b][slot] = ys[e];
            g_zs[b][slot] = zs[e];
            g_pm[b][slot] = (unsigned)(p + e);
        }
    }
    __syncthreads();   // scatter visible block-wide (global+shared fence)

    // ---------------- initial argmax over x (orig indices) -----------------
    int far;
    {
        const unsigned vb   = __float_as_uint(mv0);   // x >= 0
        const unsigned wmax = __reduce_max_sync(0xffffffffu, vb);
        const unsigned cand = (vb == wmax) ? (unsigned)mi0 : 0xFFFFFFFFu;
        const unsigned imin = __reduce_min_sync(0xffffffffu, cand);
        if (lane == 0) { s_v[0][warp] = wmax; s_i[0][warp] = imin; }
        __syncthreads();
        const unsigned tv    = (lane < NWARP) ? s_v[0][lane] : 0u;
        const unsigned tvmax = __reduce_max_sync(0xffffffffu, tv);
        const unsigned tcand = (lane < NWARP && tv == tvmax) ? s_i[0][lane]
                                                             : 0xFFFFFFFFu;
        far = (int)__reduce_min_sync(0xffffffffu, tcand);
        __syncthreads();   // everyone done with s_v[0]/s_i[0]
    }
    float cx = __ldg(&base[far]);
    float cy = __ldg(&base[NPTS + far]);
    float cz = __ldg(&base[2 * NPTS + far]);

    // -------- phase 3: load sorted x,y into registers; warp bbox -----------
    const float4* __restrict__ Xs4 = (const float4*)&g_xs[b][0];
    const float4* __restrict__ Ys4 = (const float4*)&g_ys[b][0];
    const float4* __restrict__ Zs4 = (const float4*)&g_zs[b][0];

    unsigned long long ux[2 * CHUNKS], uy[2 * CHUNKS];
    float dist[PPT];
    float bxl = 1e9f, bxh = -1e9f, byl = 1e9f, byh = -1e9f,
          bzl = 1e9f, bzh = -1e9f;
    #pragma unroll
    for (int c = 0; c < CHUNKS; c++) {
        const int i4 = warp * 256 + c * 32 + lane;   // coalesced, warp-local
        const float4 X = __ldg(&Xs4[i4]);
        const float4 Y = __ldg(&Ys4[i4]);
        const float4 Z = __ldg(&Zs4[i4]);
        PACK2(ux[2*c],     X.x, X.y);
        PACK2(ux[2*c + 1], X.z, X.w);
        PACK2(uy[2*c],     Y.x, Y.y);
        PACK2(uy[2*c + 1], Y.z, Y.w);
        bxl = fminf(bxl, fminf(fminf(X.x, X.y), fminf(X.z, X.w)));
        bxh = fmaxf(bxh, fmaxf(fmaxf(X.x, X.y), fmaxf(X.z, X.w)));
        byl = fminf(byl, fminf(fminf(Y.x, Y.y), fminf(Y.z, Y.w)));
        byh = fmaxf(byh, fmaxf(fmaxf(Y.x, Y.y), fmaxf(Y.z, Y.w)));
        bzl = fminf(bzl, fminf(fminf(Z.x, Z.y), fminf(Z.z, Z.w)));
        bzh = fmaxf(bzh, fmaxf(fmaxf(Z.x, Z.y), fmaxf(Z.z, Z.w)));
    }
    // warp-wide bbox (coords >= 0: bit order == value order)
    bxl = __uint_as_float(__reduce_min_sync(0xffffffffu, __float_as_uint(bxl)));
    byl = __uint_as_float(__reduce_min_sync(0xffffffffu, __float_as_uint(byl)));
    bzl = __uint_as_float(__reduce_min_sync(0xffffffffu, __float_as_uint(bzl)));
    bxh = __uint_as_float(__reduce_max_sync(0xffffffffu, __float_as_uint(bxh)));
    byh = __uint_as_float(__reduce_max_sync(0xffffffffu, __float_as_uint(byh)));
    bzh = __uint_as_float(__reduce_max_sync(0xffffffffu, __float_as_uint(bzh)));
    #pragma unroll
    for (int i = 0; i < PPT; i++) dist[i] = 1e10f;
    float ub = 1e10f;

    // ------------------------- FPS main loop -------------------------------
    for (int k = 0; k < NPOINT; k++) {
        if (tid == 0) s_cent[k] = far;
        const int par = k & 1;

        // skip test: conservative lower bound of d(centroid, bbox)
        const float qx = fminf(fmaxf(cx, bxl), bxh);
        const float qy = fminf(fmaxf(cy, byl), byh);
        const float qz = fminf(fmaxf(cz, bzl), bzh);
        const float ex = cx - qx, ey = cy - qy, ez = cz - qz;
        const float dlb = __fmaf_rn(ez, ez, __fmaf_rn(ey, ey, ex * ex));
        const bool skip = dlb > __fmaf_rn(ub, 1.0001f, 1e-7f);

        unsigned wmax;
        if (!skip) {
            unsigned long long ncxx, ncyy, nczz;
            PACK2(ncxx, -cx, -cx);
            PACK2(ncyy, -cy, -cy);
            PACK2(nczz, -cz, -cz);
            float mvA = -1.0f, mvB = -1.0f;
            #pragma unroll
            for (int c = 0; c < CHUNKS; c++) {
                const float4 Z = __ldg(&Zs4[warp * 256 + c * 32 + lane]);
                unsigned long long z01, z23;
                PACK2(z01, Z.x, Z.y);
                PACK2(z23, Z.z, Z.w);
                #pragma unroll
                for (int j = 0; j < 2; j++) {
                    unsigned long long dx2, dy2, dz2, t2;
                    ADD2(dx2, ux[2*c + j], ncxx);  // fadd(v,-c) == fsub(v,c)
                    ADD2(dy2, uy[2*c + j], ncyy);
                    ADD2(dz2, (j ? z23 : z01), nczz);
                    MUL2(t2, dx2, dx2);
                    FMA2(t2, dy2, dy2, t2);        // dy*dy + dx*dx
                    FMA2(t2, dz2, dz2, t2);        // dz*dz + (...) exact order
                    float t0, t1;
                    UNPACK2(t0, t1, t2);
                    const int i0 = c * 4 + 2*j;
                    const float dd0 = fminf(dist[i0],     t0);
                    const float dd1 = fminf(dist[i0 + 1], t1);
                    dist[i0]     = dd0;
                    dist[i0 + 1] = dd1;
                    mvA = fmaxf(mvA, dd0);
                    mvB = fmaxf(mvB, dd1);
                }
            }
            const float mv = fmaxf(mvA, mvB);
            wmax = __reduce_max_sync(0xffffffffu, __float_as_uint(mv));
            ub = __uint_as_float(wmax);
        } else {
            wmax = __float_as_uint(ub);   // dist unchanged -> max unchanged
        }
        if (lane == 0) s_v[par][warp] = wmax;
        __syncthreads();                                   // BAR 1

        const unsigned tv   = (lane < NWARP) ? s_v[par][lane] : 0u;
        const unsigned vmax = __reduce_max_sync(0xffffffffu, tv);

        // lazy find in warps holding the block max (orig-index tie-break)
        unsigned p = 0xFFFFFFFFu;
        float pxv = 0.f, pyv = 0.f, pzv = 0.f;
        if (wmax == vmax) {
            #pragma unroll
            for (int i = 0; i < PPT; i++) {
                if (__float_as_uint(dist[i]) == vmax) {
                    const int pos = warp * 1024 + (i >> 2) * 128
                                  + lane * 4 + (i & 3);
                    const unsigned o = __ldg(&g_pm[b][pos]);
                    if (o < p) {
                        p = o;
                        float lo, hi;
                        UNPACK2(lo, hi, ux[i >> 1]);
                        pxv = (i & 1) ? hi : lo;
                        UNPACK2(lo, hi, uy[i >> 1]);
                        pyv = (i & 1) ? hi : lo;
                        pzv = __ldg(&g_zs[b][pos]);
                    }
                }
            }
        }
        const unsigned pw = __reduce_min_sync(0xffffffffu, p);
        if (p == pw && p != 0xFFFFFFFFu) {   // unique owner thread
            s_cx[par][warp] = pxv;
            s_cy[par][warp] = pyv;
            s_cz[par][warp] = pzv;
        }
        if (lane == 0) s_i[par][warp] = pw;
        __syncthreads();                                   // BAR 2

        const unsigned ti = (lane < NWARP) ? s_i[par][lane] : 0xFFFFFFFFu;
        const unsigned fu = __reduce_min_sync(0xffffffffu, ti);
        far = (int)fu;
        const unsigned wl = __reduce_min_sync(
            0xffffffffu, (ti == fu) ? (unsigned)lane : 32u);
        cx = s_cx[par][wl];
        cy = s_cy[par][wl];
        cz = s_cz[par][wl];
    }
    __syncthreads();   // s_cent complete

    // ---- ball query: 16 warps, 64 centroids each (orig layout) ----
    for (int s = warp; s < NPOINT; s += NWARP) {
        const int c = s_cent[s];
        const float xs = __ldg(&base[c]);
        const float ys = __ldg(&base[NPTS + c]);
        const float zs = __ldg(&base[2 * NPTS + c]);
        const float snorm = __fmaf_rn(zs, zs,
                            __fmaf_rn(ys, ys, __fmul_rn(xs, xs)));

        int winner = NPTS;
        for (int j0 = 0; j0 < NPTS; j0 += 32) {
            const int j = j0 + lane;
            const float xj = __ldg(&base[j]);
            const float yj = __ldg(&base[NPTS + j]);
            const float zj = __ldg(&base[2 * NPTS + j]);
            const float dot   = __fmaf_rn(zs, zj,
                                __fmaf_rn(ys, yj, __fmul_rn(xs, xj)));
            const float dnorm = __fmaf_rn(zj, zj,
                                __fmaf_rn(yj, yj, __fmul_rn(xj, xj)));
            const float d = __fadd_rn(__fmaf_rn(-2.0f, dot, snorm), dnorm);
            const unsigned m = __ballot_sync(0xffffffffu, !(d > 0.25f));
            if (m) { winner = j0 + __ffs(m) - 1; break; }
        }
        if (lane == 0) out[b * NPOINT + s] = (float)winner;
    }
}

// ---------------------------------------------------------------------------
extern "C" void kernel_launch(void* const* d_in, const int* in_sizes, int n_in,
                              void* d_out, int out_size) {
    int xi = 0;
    for (int i = 0; i < n_in; i++) {
        if (in_sizes[i] == NBATCH * 3 * NPTS) { xi = i; break; }
    }
    const float* xyz = (const float*)d_in[xi];
    float* out = (float*)d_out;

    fps_kernel<<<NBATCH, NTHR>>>(xyz, out);
}

// round 17
// speedup vs baseline: 1.3582x; 1.3582x over previous
#include <cuda_runtime.h>
#include <cstdint>

#define NPTS   16384
#define NPOINT 1024
#define NBATCH 4
#define NTHR   1024
#define NWARP  32
#define CHUNKS 4                 // float4 chunks per thread (4 pts each)
#define PPT    16                // points per thread

// ---- packed f32x2 helpers (per-lane bit-identical to scalar rn ops) ----
#define PACK2(out, lo, hi) \
    asm("mov.b64 %0, {%1, %2};" : "=l"(out) : "f"(lo), "f"(hi))
#define UNPACK2(lo, hi, in) \
    asm("mov.b64 {%0, %1}, %2;" : "=f"(lo), "=f"(hi) : "l"(in))
#define ADD2(out, a, b) \
    asm("add.rn.f32x2 %0, %1, %2;" : "=l"(out) : "l"(a), "l"(b))
#define MUL2(out, a, b) \
    asm("mul.rn.f32x2 %0, %1, %2;" : "=l"(out) : "l"(a), "l"(b))
#define FMA2(out, a, b, c) \
    asm("fma.rn.f32x2 %0, %1, %2, %3;" : "=l"(out) : "l"(a), "l"(b), "l"(c))

// ---------------------------------------------------------------------------
// Fused FPS + ball query. One CTA (1024 thr) per batch. xyz layout [B,3,N].
// Identical algorithm/FP semantics to the validated 808us round-14 kernel,
// rebalanced to 8 warps/SMSP for latency hiding:
//  - packed f32x2 distance core, exact order t=dx*dx; t+=dy*dy; t+=dz*dz
//  - scalar fminf update + fmaxf tracking
//  - value-only REDUX reduce, lazy first-occurrence index find after vmax
//  - float32 output
// ---------------------------------------------------------------------------
__global__ void __launch_bounds__(NTHR, 1)
fps_kernel(const float* __restrict__ xyz, float* __restrict__ out) {
    __shared__ unsigned s_v[NWARP];
    __shared__ unsigned s_i[NWARP];
    __shared__ int s_cent[NPOINT];

    const int tid  = threadIdx.x;
    const int warp = tid >> 5;
    const int lane = tid & 31;
    const int b    = blockIdx.x;

    const float* __restrict__ base = xyz + (size_t)b * 3 * NPTS;
    const float4* __restrict__ X4 = (const float4*)base;
    const float4* __restrict__ Y4 = X4 + NPTS / 4;
    const ulonglong2* __restrict__ Zu2 =
        (const ulonglong2*)(base + 2 * NPTS);

    // ---- load x,y packed; initial x-argmax on the fly (x >= 0) ----
    unsigned long long ux[2 * CHUNKS], uy[2 * CHUNKS];
    float dist[PPT];
    float mv0 = -1.0f; int mi0 = 0;
    #pragma unroll
    for (int c = 0; c < CHUNKS; c++) {
        const float4 X = __ldg(&X4[c * NTHR + tid]);
        const float4 Y = __ldg(&Y4[c * NTHR + tid]);
        PACK2(ux[2*c],     X.x, X.y);
        PACK2(ux[2*c + 1], X.z, X.w);
        PACK2(uy[2*c],     Y.x, Y.y);
        PACK2(uy[2*c + 1], Y.z, Y.w);
        const int p = (c * NTHR + tid) * 4;
        if (X.x > mv0) { mv0 = X.x; mi0 = p;     }
        if (X.y > mv0) { mv0 = X.y; mi0 = p + 1; }
        if (X.z > mv0) { mv0 = X.z; mi0 = p + 2; }
        if (X.w > mv0) { mv0 = X.w; mi0 = p + 3; }
    }
    #pragma unroll
    for (int i = 0; i < PPT; i++) dist[i] = 1e10f;

    // ---- initial block argmax over x (value+index, one-time) ----
    int far;
    {
        const unsigned vb   = __float_as_uint(mv0);
        const unsigned wmax = __reduce_max_sync(0xffffffffu, vb);
        const unsigned cand = (vb == wmax) ? (unsigned)mi0 : 0xFFFFFFFFu;
        const unsigned imin = __reduce_min_sync(0xffffffffu, cand);
        if (lane == 0) { s_v[warp] = wmax; s_i[warp] = imin; }
        __syncthreads();
        const unsigned tv    = s_v[lane];
        const unsigned tvmax = __reduce_max_sync(0xffffffffu, tv);
        const unsigned tcand = (tv == tvmax) ? s_i[lane] : 0xFFFFFFFFu;
        far = (int)__reduce_min_sync(0xffffffffu, tcand);
        __syncthreads();   // s_v/s_i reusable
    }

    // ---- FPS main loop ----
    for (int k = 0; k < NPOINT; k++) {
        if (tid == 0) s_cent[k] = far;

        const float cx = __ldg(&base[far]);
        const float cy = __ldg(&base[NPTS + far]);
        const float cz = __ldg(&base[2 * NPTS + far]);
        unsigned long long ncxx, ncyy, nczz;
        PACK2(ncxx, -cx, -cx);
        PACK2(ncyy, -cy, -cy);
        PACK2(nczz, -cz, -cz);

        float mvA = -1.0f, mvB = -1.0f;
        #pragma unroll
        for (int c = 0; c < CHUNKS; c++) {
            const ulonglong2 Zu = __ldg(&Zu2[c * NTHR + tid]);
            #pragma unroll
            for (int j = 0; j < 2; j++) {
                unsigned long long dx2, dy2, dz2, t2;
                ADD2(dx2, ux[2*c + j], ncxx);   // fadd(v,-c) == fsub(v,c)
                ADD2(dy2, uy[2*c + j], ncyy);
                ADD2(dz2, (j ? Zu.y : Zu.x), nczz);
                MUL2(t2, dx2, dx2);
                FMA2(t2, dy2, dy2, t2);         // dy*dy + dx*dx
                FMA2(t2, dz2, dz2, t2);         // dz*dz + (...)  exact order
                float t0, t1;
                UNPACK2(t0, t1, t2);
                const int i0 = c * 4 + 2*j;
                const float dd0 = fminf(dist[i0],     t0);
                const float dd1 = fminf(dist[i0 + 1], t1);
                dist[i0]     = dd0;
                dist[i0 + 1] = dd1;
                mvA = fmaxf(mvA, dd0);
                mvB = fmaxf(mvB, dd1);
            }
        }
        const float mv = fmaxf(mvA, mvB);

        // ---- value-only reduction (all >= 0: bit order == value order) ----
        const unsigned vb   = __float_as_uint(mv);
        const unsigned wmax = __reduce_max_sync(0xffffffffu, vb);
        if (lane == 0) s_v[warp] = wmax;
        __syncthreads();                                   // BAR 1
        const unsigned tv   = s_v[lane];
        const unsigned vmax = __reduce_max_sync(0xffffffffu, tv);

        // ---- lazy index find: only threads holding vmax scan ----
        unsigned p = 0xFFFFFFFFu;
        if (vb == vmax) {
            #pragma unroll
            for (int i = PPT - 1; i >= 0; i--) {   // descending => first occ.
                if (__float_as_uint(dist[i]) == vmax)
                    p = (unsigned)(((i >> 2) * NTHR + tid) * 4 + (i & 3));
            }
        }
        const unsigned pw = __reduce_min_sync(0xffffffffu, p);
        if (lane == 0) s_i[warp] = pw;
        __syncthreads();                                   // BAR 2
        const unsigned ti = s_i[lane];
        far = (int)__reduce_min_sync(0xffffffffu, ti);
    }
    __syncthreads();   // s_cent complete

    // ---- ball query: 32 warps, 32 centroids each ----
    for (int s = warp; s < NPOINT; s += NWARP) {
        const int c = s_cent[s];
        const float xs = __ldg(&base[c]);
        const float ys = __ldg(&base[NPTS + c]);
        const float zs = __ldg(&base[2 * NPTS + c]);
        const float snorm = __fmaf_rn(zs, zs,
                            __fmaf_rn(ys, ys, __fmul_rn(xs, xs)));

        int winner = NPTS;
        for (int j0 = 0; j0 < NPTS; j0 += 32) {
            const int j = j0 + lane;
            const float xj = __ldg(&base[j]);
            const float yj = __ldg(&base[NPTS + j]);
            const float zj = __ldg(&base[2 * NPTS + j]);
            const float dot   = __fmaf_rn(zs, zj,
                                __fmaf_rn(ys, yj, __fmul_rn(xs, xj)));
            const float dnorm = __fmaf_rn(zj, zj,
                                __fmaf_rn(yj, yj, __fmul_rn(xj, xj)));
            const float d = __fadd_rn(__fmaf_rn(-2.0f, dot, snorm), dnorm);
            const unsigned m = __ballot_sync(0xffffffffu, !(d > 0.25f));
            if (m) { winner = j0 + __ffs(m) - 1; break; }
        }
        if (lane == 0) out[b * NPOINT + s] = (float)winner;
    }
}

// ---------------------------------------------------------------------------
extern "C" void kernel_launch(void* const* d_in, const int* in_sizes, int n_in,
                              void* d_out, int out_size) {
    int xi = 0;
    for (int i = 0; i < n_in; i++) {
        if (in_sizes[i] == NBATCH * 3 * NPTS) { xi = i; break; }
    }
    const float* xyz = (const float*)d_in[xi];
    float* out = (float*)d_out;

    fps_kernel<<<NBATCH, NTHR>>>(xyz, out);
}